// round 1
// baseline (speedup 1.0000x reference)
#include <cuda_runtime.h>

// ---------------- problem constants ----------------
#define K_CODES   1024
#define D_DIM     128
#define N_TOK     65536        // 64 * 32 * 32 tokens (BHWC order)
#define Z_ELEMS   8388608      // 64 * 128 * 32 * 32
#define EMA       0.99f
#define EPSV      1e-5f

// ---------------- output layout (flattened reference tuple, fp32) ----------------
#define Q_OFF     0            // quantized_st : 8388608
#define IDX_OFF   8388608      // idx_map      : 65536
#define L_OFF     8454144      // commitment_loss, codebook_loss : 2
#define CB_OFF    8454146      // new_codebook : 131072
#define CNT_OFF   8585218      // new_ema_count: 1024
#define EMW_OFF   8586242      // new_ema_weight: 131072  (total 8717314)

// ---------------- scratch (no allocations allowed) ----------------
__device__ float g_cbT[D_DIM * K_CODES];     // codebook transposed [d][k]
__device__ float g_cnorm[K_CODES];           // ||c_k||^2
__device__ float g_counts[K_CODES];          // encodings_sum accumulator
__device__ float g_dw[K_CODES * D_DIM];      // dw accumulator
__device__ int   g_idx[N_TOK];               // argmin indices
__device__ float g_loss;                     // sum of squared diffs
__device__ float g_weights[K_CODES];         // denominator for new_codebook

// ---------------- zero scratch (must run every launch: graph replays) ----------------
__global__ void zero_kernel() {
    int i = blockIdx.x * blockDim.x + threadIdx.x;
    if (i < K_CODES * D_DIM) g_dw[i] = 0.f;
    if (i < K_CODES)         g_counts[i] = 0.f;
    if (i == 0)              g_loss = 0.f;
}

// ---------------- transpose codebook + squared norms ----------------
__global__ void prep_kernel(const float* __restrict__ cb) {
    int k = blockIdx.x;           // 1024 blocks
    int d = threadIdx.x;          // 128 threads
    float v = cb[k * D_DIM + d];
    g_cbT[d * K_CODES + k] = v;
    float sq = v * v;
    #pragma unroll
    for (int o = 16; o; o >>= 1) sq += __shfl_xor_sync(0xffffffffu, sq, o);
    __shared__ float ws[4];
    if ((threadIdx.x & 31) == 0) ws[threadIdx.x >> 5] = sq;
    __syncthreads();
    if (threadIdx.x == 0) g_cnorm[k] = ws[0] + ws[1] + ws[2] + ws[3];
}

// ---------------- fused distance GEMM + argmin ----------------
// Block: 256 threads, tile = 128 tokens x 128 codes, loop over 8 code tiles.
// dist(n,k) = ||c_k||^2 - 2 * z_n . c_k   (||z||^2 constant per token)
__global__ void __launch_bounds__(256, 1) argmin_kernel(const float* __restrict__ z) {
    extern __shared__ float sm[];
    float* zt = sm;                  // [128 d][128 tok]
    float* ct = sm + 128 * 128;      // [128 d][128 code]

    const int m0 = blockIdx.x * 128;     // token base (tile fully inside one batch image)
    const int b  = m0 >> 10;             // 1024 tokens per image
    const int s0 = m0 & 1023;
    const size_t zbase = (size_t)b * 131072 + s0;

    // load z tile transposed: zt[d][t] = z[b, d, s0 + t]  (coalesced in t)
    for (int u = threadIdx.x; u < 128 * 32; u += 256) {
        int d = u >> 5, t4 = (u & 31) << 2;
        *(float4*)&zt[d * 128 + t4] =
            *(const float4*)&z[zbase + (size_t)d * 1024 + t4];
    }

    const int tx = threadIdx.x & 15;     // code dim (8 codes each)
    const int ty = threadIdx.x >> 4;     // token dim (8 tokens each)

    float best[8];
    int   bidx[8];
    #pragma unroll
    for (int i = 0; i < 8; i++) { best[i] = 3.4e38f; bidx[i] = 0; }

    for (int k0 = 0; k0 < K_CODES; k0 += 128) {
        __syncthreads();
        for (int u = threadIdx.x; u < 128 * 32; u += 256) {
            int d = u >> 5, c4 = (u & 31) << 2;
            *(float4*)&ct[d * 128 + c4] =
                *(const float4*)&g_cbT[d * K_CODES + k0 + c4];
        }
        __syncthreads();

        float acc[8][8];
        #pragma unroll
        for (int i = 0; i < 8; i++)
            #pragma unroll
            for (int j = 0; j < 8; j++) acc[i][j] = 0.f;

        #pragma unroll 4
        for (int kk = 0; kk < 128; kk++) {
            float4 a0 = *(float4*)&zt[kk * 128 + ty * 8];
            float4 a1 = *(float4*)&zt[kk * 128 + ty * 8 + 4];
            float4 b0 = *(float4*)&ct[kk * 128 + tx * 8];
            float4 b1 = *(float4*)&ct[kk * 128 + tx * 8 + 4];
            float a[8] = {a0.x, a0.y, a0.z, a0.w, a1.x, a1.y, a1.z, a1.w};
            float c[8] = {b0.x, b0.y, b0.z, b0.w, b1.x, b1.y, b1.z, b1.w};
            #pragma unroll
            for (int i = 0; i < 8; i++)
                #pragma unroll
                for (int j = 0; j < 8; j++)
                    acc[i][j] += a[i] * c[j];
        }

        // fold tile into running argmin (ascending j keeps first-index tie-break)
        #pragma unroll
        for (int j = 0; j < 8; j++) {
            int c = k0 + tx * 8 + j;
            float cn = __ldg(&g_cnorm[c]);
            #pragma unroll
            for (int i = 0; i < 8; i++) {
                float dist = cn - 2.f * acc[i][j];
                if (dist < best[i]) { best[i] = dist; bidx[i] = c; }
            }
        }
    }

    // reduce across the 16 tx-threads (stay within half-warp: xor < 16)
    #pragma unroll
    for (int i = 0; i < 8; i++) {
        float v = best[i];
        int   id = bidx[i];
        #pragma unroll
        for (int off = 8; off; off >>= 1) {
            float ov = __shfl_xor_sync(0xffffffffu, v, off);
            int   oi = __shfl_xor_sync(0xffffffffu, id, off);
            if (ov < v || (ov == v && oi < id)) { v = ov; id = oi; }
        }
        if (tx == 0) g_idx[m0 + ty * 8 + i] = id;
    }
}

// ---------------- gather quantized + loss + counts + idx output ----------------
// 8 tokens per 256-thread block; one warp per token, float4 per lane.
__global__ void quant_kernel(const float* __restrict__ z,
                             const float* __restrict__ cb,
                             float* __restrict__ out) {
    int n    = blockIdx.x * 8 + (threadIdx.x >> 5);
    int lane = threadIdx.x & 31;
    int k    = g_idx[n];

    float4 q  = *(const float4*)&cb[k * D_DIM + lane * 4];
    size_t off = (size_t)n * D_DIM + lane * 4;
    *(float4*)&out[Q_OFF + off] = q;

    // loss compares BHWC-flat quantized against the SAME linear index of z (raw view)
    float4 zz = *(const float4*)&z[off];
    float dx = q.x - zz.x, dy = q.y - zz.y, dz = q.z - zz.z, dw = q.w - zz.w;
    float s = dx * dx + dy * dy + dz * dz + dw * dw;
    #pragma unroll
    for (int o = 16; o; o >>= 1) s += __shfl_xor_sync(0xffffffffu, s, o);

    __shared__ float ws[8];
    if (lane == 0) {
        ws[threadIdx.x >> 5] = s;
        atomicAdd(&g_counts[k], 1.f);
        out[IDX_OFF + n] = (float)k;
    }
    __syncthreads();
    if (threadIdx.x == 0) {
        float t = 0.f;
        #pragma unroll
        for (int i = 0; i < 8; i++) t += ws[i];
        atomicAdd(&g_loss, t);
    }
}

// ---------------- dw scatter: dw[k][d] += z_flat[n][d] ----------------
// Linear over z (BCHW) so global reads are coalesced; atomics spread over codes.
__global__ void dw_kernel(const float* __restrict__ z) {
    int i = blockIdx.x * blockDim.x + threadIdx.x;   // < 8388608
    int s = i & 1023;
    int d = (i >> 10) & 127;
    int b = i >> 17;
    int n = (b << 10) + s;
    int k = g_idx[n];
    atomicAdd(&g_dw[k * D_DIM + d], z[i]);
}

// ---------------- EMA count update, n-sum, weights, losses ----------------
__global__ void finalize1_kernel(const float* __restrict__ ema_count,
                                 float* __restrict__ out) {
    int k = threadIdx.x;   // 1024 threads, 1 block
    float c = EMA * ema_count[k] + (1.f - EMA) * g_counts[k];
    out[CNT_OFF + k] = c;

    __shared__ float sm[1024];
    sm[k] = c;
    __syncthreads();
    for (int o = 512; o; o >>= 1) {
        if (k < o) sm[k] += sm[k + o];
        __syncthreads();
    }
    float n = sm[0];
    g_weights[k] = (c + EPSV) / (n + K_CODES * EPSV) * n;

    if (k == 0) {
        float L = g_loss / 8388608.f;
        out[L_OFF]     = L;   // commitment_loss
        out[L_OFF + 1] = L;   // codebook_loss (numerically identical)
    }
}

// ---------------- EMA weight update + new codebook ----------------
__global__ void finalize2_kernel(const float* __restrict__ ema_weight,
                                 float* __restrict__ out) {
    int i = blockIdx.x * blockDim.x + threadIdx.x;   // < 131072
    int k = i >> 7;
    float w = EMA * ema_weight[i] + (1.f - EMA) * g_dw[i];
    out[EMW_OFF + i] = w;
    out[CB_OFF + i]  = w / g_weights[k];
}

// ---------------- launch ----------------
extern "C" void kernel_launch(void* const* d_in, const int* in_sizes, int n_in,
                              void* d_out, int out_size) {
    const float* z          = (const float*)d_in[0];
    const float* cb         = (const float*)d_in[1];
    const float* ema_count  = (const float*)d_in[2];
    const float* ema_weight = (const float*)d_in[3];
    float* out = (float*)d_out;

    cudaFuncSetAttribute(argmin_kernel,
                         cudaFuncAttributeMaxDynamicSharedMemorySize, 131072);

    zero_kernel<<<512, 256>>>();
    prep_kernel<<<K_CODES, D_DIM>>>(cb);
    argmin_kernel<<<N_TOK / 128, 256, 131072>>>(z);
    quant_kernel<<<N_TOK / 8, 256>>>(z, cb, out);
    dw_kernel<<<Z_ELEMS / 256, 256>>>(z);
    finalize1_kernel<<<1, 1024>>>(ema_count, out);
    finalize2_kernel<<<512, 256>>>(ema_weight, out);
}